// round 12
// baseline (speedup 1.0000x reference)
#include <cuda_runtime.h>
#include <cstdint>

typedef unsigned long long ull;

__device__ __forceinline__ ull pack2(float lo, float hi) {
    ull r; asm("mov.b64 %0, {%1, %2};" : "=l"(r) : "f"(lo), "f"(hi)); return r;
}
__device__ __forceinline__ void unpack2(ull v, float& lo, float& hi) {
    asm("mov.b64 {%0, %1}, %2;" : "=f"(lo), "=f"(hi) : "l"(v));
}
__device__ __forceinline__ void fma2(ull& d, ull a, ull b) {
    asm("fma.rn.f32x2 %0, %1, %2, %0;" : "+l"(d) : "l"(a), "l"(b));
}
__device__ __forceinline__ uint32_t s2u(const void* p) {
    return (uint32_t)__cvta_generic_to_shared(p);
}
__device__ __forceinline__ void cpa4(uint32_t dst, const float* src) {
    asm volatile("cp.async.ca.shared.global [%0], [%1], 4;" :: "r"(dst), "l"(src));
}
#define CP_COMMIT() asm volatile("cp.async.commit_group;" ::: "memory")
#define CP_WAIT0()  asm volatile("cp.async.wait_group 0;" ::: "memory")

#define NB 256
#define LC 400
#define LQ 50
#define DD 128
#define SM_TOT 27156   // floats: S 20000 | A/stb 6600 | sc 400 | sq 52 | mxc 52 | invc 52

__global__ __launch_bounds__(512, 2)
void cqa5_kernel(const float* __restrict__ g_xc, const float* __restrict__ g_xq,
                 const float* __restrict__ g_W0, const float* __restrict__ g_W1,
                 const float* __restrict__ g_W2, const int* __restrict__ g_clen,
                 const int* __restrict__ g_qlen, float* __restrict__ out)
{
    extern __shared__ float sm[];
    float* S    = sm;            // 400*50 packed
    float* A    = sm + 20000;    // 6600: phase3 stb (50x129) / phase5 A (50x132)
    float* sc   = sm + 26600;
    float* sq   = sm + 27000;
    float* mxc  = sm + 27052;
    float* invc = sm + 27104;
    // phase-1 staging lives inside S (dead until phase-1 writeback)
    float* stA0 = S;             // 16*404 = 6464 (16B-aligned rows)
    float* stA1 = S + 6464;
    float* stQ0 = S + 12928;     // 16*51 = 816
    float* stQ1 = S + 13744;

    const int b = blockIdx.x;
    const int t = threadIdx.x, lane = t & 31, w = t >> 5;
    const float* xcb = g_xc + (size_t)b * LC * DD;
    const float* xqb = g_xq + (size_t)b * LQ * DD;
    const int clen = g_clen[b];
    const int qlen = g_qlen[b];

    float* outSB = out + (size_t)NB * LC * 4 * DD;
    float* outST = outSB + (size_t)NB * LC * LQ;

    // ---------------- Phase 0: sc[c] = xc.W0, sq[q] = xq.W1 ------------------
    {
        float4 w0 = __ldg((const float4*)g_W0 + lane);
        #pragma unroll 1
        for (int r = 0; r < 25; r++) {
            int c = w + 16 * r;
            float4 v = __ldg((const float4*)(xcb + (size_t)c * DD) + lane);
            float p = v.x * w0.x + v.y * w0.y + v.z * w0.z + v.w * w0.w;
            #pragma unroll
            for (int o = 16; o; o >>= 1) p += __shfl_xor_sync(~0u, p, o);
            if (!lane) sc[c] = p;
        }
        float4 w1 = __ldg((const float4*)g_W1 + lane);
        #pragma unroll
        for (int r = 0; r < 4; r++) {
            int q = w + 16 * r;
            if (q < LQ) {
                float4 v = __ldg((const float4*)(xqb + (size_t)q * DD) + lane);
                float p = v.x * w1.x + v.y * w1.y + v.z * w1.z + v.w * w1.w;
                #pragma unroll
                for (int o = 16; o; o >>= 1) p += __shfl_xor_sync(~0u, p, o);
                if (!lane) sq[q] = p;
            }
        }
    }

    // ---------------- Phase 1: S = xc @ (W2*xq)^T, 8 slices x 16d ------------
    ull acc[4][5];
    #pragma unroll
    for (int i = 0; i < 4; i++)
        #pragma unroll
        for (int j = 0; j < 5; j++) acc[i][j] = 0ull;
    const int ct = t / 10, qt = t - ct * 10;
    const bool act = t < 500;
    const int cb = ct * 8, qb = qt * 5;

    auto issue = [&](int s) {
        const int d0 = s * 16;
        float* bA = (s & 1) ? stA1 : stA0;
        float* bQ = (s & 1) ? stQ1 : stQ0;
        #pragma unroll 1
        for (int i = t; i < LC * 16; i += 512) {
            int c = i >> 4, dd = i & 15;
            cpa4(s2u(bA + dd * 404 + c), xcb + (size_t)c * DD + d0 + dd);
        }
        CP_COMMIT();
        #pragma unroll 1
        for (int i = t; i < LQ * 16; i += 512) {
            int q = i >> 4, dd = i & 15;
            bQ[dd * 51 + q] = xqb[q * DD + d0 + dd] * __ldg(g_W2 + d0 + dd);
        }
    };

    __syncthreads();
    issue(0);
    #pragma unroll 1
    for (int s = 0; s < 8; s++) {
        CP_WAIT0();
        __syncthreads();            // slice s staged & visible; prev compute done
        if (s < 7) issue(s + 1);    // overlaps with compute below
        const float* bA = (s & 1) ? stA1 : stA0;
        const float* bQ = (s & 1) ? stQ1 : stQ0;
        if (act) {
            #pragma unroll
            for (int dd = 0; dd < 16; dd++) {
                union { float4 f; ull u[2]; } X0, X1;
                X0.f = *(const float4*)&bA[dd * 404 + cb];
                X1.f = *(const float4*)&bA[dd * 404 + cb + 4];
                #pragma unroll
                for (int j = 0; j < 5; j++) {
                    float xv = bQ[dd * 51 + qb + j];
                    ull bb = pack2(xv, xv);
                    fma2(acc[0][j], X0.u[0], bb);
                    fma2(acc[1][j], X0.u[1], bb);
                    fma2(acc[2][j], X1.u[0], bb);
                    fma2(acc[3][j], X1.u[1], bb);
                }
            }
        }
    }
    __syncthreads();
    if (act) {
        #pragma unroll
        for (int i = 0; i < 4; i++) {
            int c = cb + 2 * i;
            float s0 = sc[c], s1 = sc[c + 1];
            #pragma unroll
            for (int j = 0; j < 5; j++) {
                float lo, hi; unpack2(acc[i][j], lo, hi);
                int q = qb + j;
                S[c * 50 + q]       = lo + s0 + sq[q];
                S[(c + 1) * 50 + q] = hi + s1 + sq[q];
            }
        }
    }
    __syncthreads();

    // ---------------- Phase 2: column (over c) softmax stats -----------------
    #pragma unroll 1
    for (int r = 0; r < 4; r++) {
        int q = w + 16 * r;
        if (q < LQ) {
            float m = -1e30f, s = 0.f;
            for (int c = lane; c < clen; c += 32) {
                float v = S[c * 50 + q];
                if (v > m) { s = s * __expf(m - v) + 1.f; m = v; }
                else       { s += __expf(v - m); }
            }
            #pragma unroll
            for (int o = 16; o; o >>= 1) {
                float m2 = __shfl_xor_sync(~0u, m, o);
                float s2 = __shfl_xor_sync(~0u, s, o);
                if (m2 > m) { s = s * __expf(m - m2) + s2; m = m2; }
                else        { s += s2 * __expf(m2 - m); }
            }
            if (!lane) { mxc[q] = m; invc[q] = 1.f / s; }
        }
    }
    __syncthreads();

    // ------ Phase 3: S_T out + A = S_T @ x_cont (warp-groups split cc) -------
    {
        float* stb = A;   // 50*129 = 6450 <= 6600
        const int g  = w >> 3;          // cc-half group
        const int wq = w & 7;
        const int nq = (wq < 2) ? 7 : 6;   // q = wq + 8j covers 0..49
        ull accA[7][2];
        #pragma unroll
        for (int j = 0; j < 7; j++) { accA[j][0] = 0ull; accA[j][1] = 0ull; }
        float* ST_b = outST + (size_t)b * LQ * LC;

        #pragma unroll 1
        for (int c0 = 0; c0 < LC; c0 += 128) {
            const int CHN = (LC - c0 >= 128) ? 128 : 16;
            __syncthreads();
            if (CHN == 128) {
                for (int i = t; i < LQ * 128; i += 512) {
                    int q = i >> 7, cc = i & 127, c = c0 + cc;
                    float v = (c < clen) ? __expf(S[c * 50 + q] - mxc[q]) * invc[q] : 0.f;
                    stb[q * 129 + cc] = v;
                    ST_b[(size_t)q * LC + c] = v;
                }
            } else {
                for (int i = t; i < LQ * 16; i += 512) {
                    int q = i >> 4, cc = i & 15, c = c0 + cc;
                    float v = (c < clen) ? __expf(S[c * 50 + q] - mxc[q]) * invc[q] : 0.f;
                    stb[q * 129 + cc] = v;
                    ST_b[(size_t)q * LC + c] = v;
                }
            }
            __syncthreads();
            const int ccb = g * (CHN >> 1);
            const int cce = ccb + (CHN >> 1);
            #pragma unroll 1
            for (int cc = ccb; cc < cce; cc += 4) {
                union { float4 f; ull u[2]; } X0, X1, X2, X3;
                X0.f = __ldg((const float4*)(xcb + (size_t)(c0 + cc) * DD) + lane);
                X1.f = __ldg((const float4*)(xcb + (size_t)(c0 + cc + 1) * DD) + lane);
                X2.f = __ldg((const float4*)(xcb + (size_t)(c0 + cc + 2) * DD) + lane);
                X3.f = __ldg((const float4*)(xcb + (size_t)(c0 + cc + 3) * DD) + lane);
                #pragma unroll
                for (int j = 0; j < 7; j++) {
                    if (j < nq) {
                        const float* sp = &stb[(wq + 8 * j) * 129 + cc];
                        ull p0 = pack2(sp[0], sp[0]);
                        ull p1 = pack2(sp[1], sp[1]);
                        ull p2 = pack2(sp[2], sp[2]);
                        ull p3 = pack2(sp[3], sp[3]);
                        fma2(accA[j][0], X0.u[0], p0);
                        fma2(accA[j][1], X0.u[1], p0);
                        fma2(accA[j][0], X1.u[0], p1);
                        fma2(accA[j][1], X1.u[1], p1);
                        fma2(accA[j][0], X2.u[0], p2);
                        fma2(accA[j][1], X2.u[1], p2);
                        fma2(accA[j][0], X3.u[0], p3);
                        fma2(accA[j][1], X3.u[1], p3);
                    }
                }
            }
        }
        __syncthreads();   // stb dead; A region reusable
        if (g == 0) {
            #pragma unroll
            for (int j = 0; j < 7; j++) {
                if (j < nq) {
                    union { float4 f; ull u[2]; } R;
                    R.u[0] = accA[j][0]; R.u[1] = accA[j][1];
                    *(float4*)&A[(wq + 8 * j) * 132 + lane * 4] = R.f;
                }
            }
        }
        __syncthreads();
        if (g == 1) {
            #pragma unroll
            for (int j = 0; j < 7; j++) {
                if (j < nq) {
                    union { float4 f; ull u[2]; } R;
                    R.u[0] = accA[j][0]; R.u[1] = accA[j][1];
                    float4 cur = *(const float4*)&A[(wq + 8 * j) * 132 + lane * 4];
                    R.f.x += cur.x; R.f.y += cur.y; R.f.z += cur.z; R.f.w += cur.w;
                    *(float4*)&A[(wq + 8 * j) * 132 + lane * 4] = R.f;
                }
            }
        }
    }
    __syncthreads();

    // ---------------- Phase 4: row softmax -> S_bar in place -----------------
    #pragma unroll 1
    for (int r = 0; r < 25; r++) {
        int c = w + 16 * r;
        int q2 = lane + 32;
        float v1 = S[c * 50 + lane];
        float v2 = (q2 < LQ) ? S[c * 50 + q2] : 0.f;
        float m = (lane < qlen) ? v1 : -1e30f;
        if (q2 < LQ && q2 < qlen) m = fmaxf(m, v2);
        #pragma unroll
        for (int o = 16; o; o >>= 1) m = fmaxf(m, __shfl_xor_sync(~0u, m, o));
        float e1 = (lane < qlen) ? __expf(v1 - m) : 0.f;
        float e2 = (q2 < LQ && q2 < qlen) ? __expf(v2 - m) : 0.f;
        float s = e1 + e2;
        #pragma unroll
        for (int o = 16; o; o >>= 1) s += __shfl_xor_sync(~0u, s, o);
        float r1 = 1.f / s;
        e1 *= r1; e2 *= r1;
        S[c * 50 + lane] = e1;
        float* row = outSB + (size_t)(b * LC + c) * LQ;
        row[lane] = e1;
        if (q2 < LQ) { S[c * 50 + q2] = e2; row[q2] = e2; }
    }
    __syncthreads();

    // ---------------- Phase 5: c2q = Sbar@xq, q2c = Sbar@A, concat (kmax=6) --
    #pragma unroll 1
    for (int pass = 0; pass < 5; pass++) {
        const int kmax = (pass < 4) ? 6 : 1;
        ull a1[6][2], a2[6][2];
        #pragma unroll
        for (int k = 0; k < 6; k++) {
            a1[k][0] = a1[k][1] = 0ull;
            a2[k][0] = a2[k][1] = 0ull;
        }
        const int cbase = pass * 96 + w;

        #pragma unroll 1
        for (int q = 0; q < LQ; q += 2) {
            union { float4 f; ull u[2]; } XQ0, XQ1, AV0, AV1;
            XQ0.f = __ldg((const float4*)(xqb + (size_t)q * DD) + lane);
            XQ1.f = __ldg((const float4*)(xqb + (size_t)(q + 1) * DD) + lane);
            AV0.f = *(const float4*)&A[q * 132 + lane * 4];
            AV1.f = *(const float4*)&A[(q + 1) * 132 + lane * 4];
            #pragma unroll
            for (int k = 0; k < 6; k++) {
                if (k < kmax) {
                    float2 sv = *(const float2*)&S[(cbase + 16 * k) * 50 + q];
                    ull s0 = pack2(sv.x, sv.x);
                    ull s1 = pack2(sv.y, sv.y);
                    fma2(a1[k][0], XQ0.u[0], s0);
                    fma2(a1[k][1], XQ0.u[1], s0);
                    fma2(a2[k][0], AV0.u[0], s0);
                    fma2(a2[k][1], AV0.u[1], s0);
                    fma2(a1[k][0], XQ1.u[0], s1);
                    fma2(a1[k][1], XQ1.u[1], s1);
                    fma2(a2[k][0], AV1.u[0], s1);
                    fma2(a2[k][1], AV1.u[1], s1);
                }
            }
        }
        #pragma unroll
        for (int k = 0; k < 6; k++) {
            if (k < kmax) {
                int c = cbase + 16 * k;
                float4 xcv = __ldg((const float4*)(xcb + (size_t)c * DD) + lane);
                union { float4 f; ull u[2]; } C2Q, Q2C;
                C2Q.u[0] = a1[k][0]; C2Q.u[1] = a1[k][1];
                Q2C.u[0] = a2[k][0]; Q2C.u[1] = a2[k][1];
                float* base = out + ((size_t)b * LC + c) * (4 * DD) + lane * 4;
                *(float4*)(base)       = xcv;
                *(float4*)(base + 128) = C2Q.f;
                *(float4*)(base + 256) = make_float4(xcv.x * C2Q.f.x, xcv.y * C2Q.f.y,
                                                     xcv.z * C2Q.f.z, xcv.w * C2Q.f.w);
                *(float4*)(base + 384) = make_float4(xcv.x * Q2C.f.x, xcv.y * Q2C.f.y,
                                                     xcv.z * Q2C.f.z, xcv.w * Q2C.f.w);
            }
        }
    }
}

extern "C" void kernel_launch(void* const* d_in, const int* in_sizes, int n_in,
                              void* d_out, int out_size)
{
    const float* xc  = (const float*)d_in[0];
    const float* xq  = (const float*)d_in[1];
    const float* W0  = (const float*)d_in[2];
    const float* W1  = (const float*)d_in[3];
    const float* W2  = (const float*)d_in[4];
    const int* clen  = (const int*)d_in[5];
    const int* qlen  = (const int*)d_in[6];
    float* out = (float*)d_out;

    const size_t smem = (size_t)SM_TOT * sizeof(float);  // 108624 B
    cudaFuncSetAttribute(cqa5_kernel, cudaFuncAttributeMaxDynamicSharedMemorySize,
                         (int)smem);
    cqa5_kernel<<<NB, 512, smem>>>(xc, xq, W0, W1, W2, clen, qlen, out);
}

// round 13
// speedup vs baseline: 1.1589x; 1.1589x over previous
#include <cuda_runtime.h>
#include <cstdint>

typedef unsigned long long ull;

__device__ __forceinline__ ull pack2(float lo, float hi) {
    ull r; asm("mov.b64 %0, {%1, %2};" : "=l"(r) : "f"(lo), "f"(hi)); return r;
}
__device__ __forceinline__ void unpack2(ull v, float& lo, float& hi) {
    asm("mov.b64 {%0, %1}, %2;" : "=f"(lo), "=f"(hi) : "l"(v));
}
__device__ __forceinline__ void fma2(ull& d, ull a, ull b) {
    asm("fma.rn.f32x2 %0, %1, %2, %0;" : "+l"(d) : "l"(a), "l"(b));
}
__device__ __forceinline__ uint32_t s2u(const void* p) {
    return (uint32_t)__cvta_generic_to_shared(p);
}
__device__ __forceinline__ void cpa4(uint32_t dst, const float* src) {
    asm volatile("cp.async.ca.shared.global [%0], [%1], 4;" :: "r"(dst), "l"(src));
}
#define CP_COMMIT() asm volatile("cp.async.commit_group;" ::: "memory")
#define CP_WAIT0()  asm volatile("cp.async.wait_group 0;" ::: "memory")

#define NB 256
#define LC 400
#define LQ 50
#define DD 128
#define SM_TOT 27156   // floats: S 20000 | A/stb/xqW2T 6600 | sc 400 | sq 52 | mxc 52 | invc 52

__global__ __launch_bounds__(512, 2)
void cqa6_kernel(const float* __restrict__ g_xc, const float* __restrict__ g_xq,
                 const float* __restrict__ g_W0, const float* __restrict__ g_W1,
                 const float* __restrict__ g_W2, const int* __restrict__ g_clen,
                 const int* __restrict__ g_qlen, float* __restrict__ out)
{
    extern __shared__ float sm[];
    float* S    = sm;            // 400*50 packed
    float* A    = sm + 20000;    // 6600: ph0-1 xqW2T (128x51) / ph3 stb (50x129) / ph5 A (50x132)
    float* sc   = sm + 26600;
    float* sq   = sm + 27000;
    float* mxc  = sm + 27052;
    float* invc = sm + 27104;
    float* xqW2T = A;            // [d][q], stride 51, 128*51 = 6528
    // phase-1 xc staging lives inside S (dead until phase-1 writeback)
    float* stA0 = S;             // 8*404 = 3232 (16B-aligned rows)
    float* stA1 = S + 3232;

    const int b = blockIdx.x;
    const int t = threadIdx.x, lane = t & 31, w = t >> 5;
    const float* xcb = g_xc + (size_t)b * LC * DD;
    const float* xqb = g_xq + (size_t)b * LQ * DD;
    const int clen = g_clen[b];
    const int qlen = g_qlen[b];

    float* outSB = out + (size_t)NB * LC * 4 * DD;
    float* outST = outSB + (size_t)NB * LC * LQ;

    // ---- Phase 0: sc[c] = xc.W0, sq[q] = xq.W1, xqW2T[d][q] = xq[q][d]*W2[d]
    {
        float4 w0 = __ldg((const float4*)g_W0 + lane);
        #pragma unroll 2
        for (int r = 0; r < 25; r++) {
            int c = w + 16 * r;
            float4 v = __ldg((const float4*)(xcb + (size_t)c * DD) + lane);
            float p = v.x * w0.x + v.y * w0.y + v.z * w0.z + v.w * w0.w;
            #pragma unroll
            for (int o = 16; o; o >>= 1) p += __shfl_xor_sync(~0u, p, o);
            if (!lane) sc[c] = p;
        }
        float4 w1 = __ldg((const float4*)g_W1 + lane);
        #pragma unroll
        for (int r = 0; r < 4; r++) {
            int q = w + 16 * r;
            if (q < LQ) {
                float4 v = __ldg((const float4*)(xqb + (size_t)q * DD) + lane);
                float p = v.x * w1.x + v.y * w1.y + v.z * w1.z + v.w * w1.w;
                #pragma unroll
                for (int o = 16; o; o >>= 1) p += __shfl_xor_sync(~0u, p, o);
                if (!lane) sq[q] = p;
            }
        }
        // xqW2T fill: i indexes (q, d4-group)
        #pragma unroll 1
        for (int i = t; i < LQ * 32; i += 512) {
            int q = i >> 5, d4 = i & 31;
            float4 v  = __ldg((const float4*)(xqb + (size_t)q * DD) + d4);
            float4 w2 = __ldg((const float4*)g_W2 + d4);
            xqW2T[(d4 * 4 + 0) * 51 + q] = v.x * w2.x;
            xqW2T[(d4 * 4 + 1) * 51 + q] = v.y * w2.y;
            xqW2T[(d4 * 4 + 2) * 51 + q] = v.z * w2.z;
            xqW2T[(d4 * 4 + 3) * 51 + q] = v.w * w2.w;
        }
    }

    // ---------------- Phase 1: S = xc @ (W2*xq)^T, cp.async double-buffered --
    ull acc[4][5];
    #pragma unroll
    for (int i = 0; i < 4; i++)
        #pragma unroll
        for (int j = 0; j < 5; j++) acc[i][j] = 0ull;
    const int ct = t / 10, qt = t - ct * 10;
    const bool act = t < 500;
    const int cb = ct * 8, qb = qt * 5;

    auto issue = [&](int s) {
        const int d0 = s * 8;
        float* bA = (s & 1) ? stA1 : stA0;
        #pragma unroll 1
        for (int i = t; i < LC * 8; i += 512) {
            int c = i >> 3, dd = i & 7;
            cpa4(s2u(bA + dd * 404 + c), xcb + (size_t)c * DD + d0 + dd);
        }
        CP_COMMIT();
    };

    __syncthreads();   // phase-0 writes (incl. xqW2T) visible
    issue(0);
    #pragma unroll 1
    for (int s = 0; s < 16; s++) {
        CP_WAIT0();
        __syncthreads();            // slice s staged & visible; prev compute done
        if (s < 15) issue(s + 1);   // overlaps with compute below
        const float* bA = (s & 1) ? stA1 : stA0;
        const float* bQ = xqW2T + (s * 8) * 51;
        if (act) {
            #pragma unroll
            for (int dd = 0; dd < 8; dd++) {
                union { float4 f; ull u[2]; } X0, X1;
                X0.f = *(const float4*)&bA[dd * 404 + cb];
                X1.f = *(const float4*)&bA[dd * 404 + cb + 4];
                #pragma unroll
                for (int j = 0; j < 5; j++) {
                    float xv = bQ[dd * 51 + qb + j];
                    ull bb = pack2(xv, xv);
                    fma2(acc[0][j], X0.u[0], bb);
                    fma2(acc[1][j], X0.u[1], bb);
                    fma2(acc[2][j], X1.u[0], bb);
                    fma2(acc[3][j], X1.u[1], bb);
                }
            }
        }
    }
    __syncthreads();
    if (act) {
        #pragma unroll
        for (int i = 0; i < 4; i++) {
            int c = cb + 2 * i;
            float s0 = sc[c], s1 = sc[c + 1];
            #pragma unroll
            for (int j = 0; j < 5; j++) {
                float lo, hi; unpack2(acc[i][j], lo, hi);
                int q = qb + j;
                S[c * 50 + q]       = lo + s0 + sq[q];
                S[(c + 1) * 50 + q] = hi + s1 + sq[q];
            }
        }
    }
    __syncthreads();

    // ---------------- Phase 2: column (over c) softmax stats -----------------
    #pragma unroll 1
    for (int r = 0; r < 4; r++) {
        int q = w + 16 * r;
        if (q < LQ) {
            float m = -1e30f, s = 0.f;
            for (int c = lane; c < clen; c += 32) {
                float v = S[c * 50 + q];
                if (v > m) { s = s * __expf(m - v) + 1.f; m = v; }
                else       { s += __expf(v - m); }
            }
            #pragma unroll
            for (int o = 16; o; o >>= 1) {
                float m2 = __shfl_xor_sync(~0u, m, o);
                float s2 = __shfl_xor_sync(~0u, s, o);
                if (m2 > m) { s = s * __expf(m - m2) + s2; m = m2; }
                else        { s += s2 * __expf(m2 - m); }
            }
            if (!lane) { mxc[q] = m; invc[q] = 1.f / s; }
        }
    }
    __syncthreads();

    // ---------------- Phase 3: S_T out + A = S_T @ x_cont (regs) -------------
    {
        float* stb = A;   // 50*129 = 6450 <= 6600  (xqW2T dead now)
        const int nq = (w < 2) ? 4 : 3;   // q = w + 16j
        ull accA[4][2];
        #pragma unroll
        for (int j = 0; j < 4; j++) { accA[j][0] = 0ull; accA[j][1] = 0ull; }
        float* ST_b = outST + (size_t)b * LQ * LC;

        #pragma unroll 1
        for (int c0 = 0; c0 < LC; c0 += 128) {
            const int CHN = (LC - c0 >= 128) ? 128 : 16;
            __syncthreads();
            if (CHN == 128) {
                for (int i = t; i < LQ * 128; i += 512) {
                    int q = i >> 7, cc = i & 127, c = c0 + cc;
                    float v = (c < clen) ? __expf(S[c * 50 + q] - mxc[q]) * invc[q] : 0.f;
                    stb[q * 129 + cc] = v;
                    ST_b[(size_t)q * LC + c] = v;
                }
            } else {
                for (int i = t; i < LQ * 16; i += 512) {
                    int q = i >> 4, cc = i & 15, c = c0 + cc;
                    float v = (c < clen) ? __expf(S[c * 50 + q] - mxc[q]) * invc[q] : 0.f;
                    stb[q * 129 + cc] = v;
                    ST_b[(size_t)q * LC + c] = v;
                }
            }
            __syncthreads();
            #pragma unroll 1
            for (int cc = 0; cc < CHN; cc += 4) {
                union { float4 f; ull u[2]; } X0, X1, X2, X3;
                X0.f = __ldg((const float4*)(xcb + (size_t)(c0 + cc) * DD) + lane);
                X1.f = __ldg((const float4*)(xcb + (size_t)(c0 + cc + 1) * DD) + lane);
                X2.f = __ldg((const float4*)(xcb + (size_t)(c0 + cc + 2) * DD) + lane);
                X3.f = __ldg((const float4*)(xcb + (size_t)(c0 + cc + 3) * DD) + lane);
                #pragma unroll
                for (int j = 0; j < 4; j++) {
                    if (j < nq) {
                        const float* sp = &stb[(w + 16 * j) * 129 + cc];
                        ull p0 = pack2(sp[0], sp[0]);
                        ull p1 = pack2(sp[1], sp[1]);
                        ull p2 = pack2(sp[2], sp[2]);
                        ull p3 = pack2(sp[3], sp[3]);
                        fma2(accA[j][0], X0.u[0], p0);
                        fma2(accA[j][1], X0.u[1], p0);
                        fma2(accA[j][0], X1.u[0], p1);
                        fma2(accA[j][1], X1.u[1], p1);
                        fma2(accA[j][0], X2.u[0], p2);
                        fma2(accA[j][1], X2.u[1], p2);
                        fma2(accA[j][0], X3.u[0], p3);
                        fma2(accA[j][1], X3.u[1], p3);
                    }
                }
            }
        }
        __syncthreads();   // stb dead; A region reusable
        #pragma unroll
        for (int j = 0; j < 4; j++) {
            if (j < nq) {
                union { float4 f; ull u[2]; } R;
                R.u[0] = accA[j][0]; R.u[1] = accA[j][1];
                *(float4*)&A[(w + 16 * j) * 132 + lane * 4] = R.f;
            }
        }
    }
    __syncthreads();

    // ---------------- Phase 4: row softmax -> S_bar in place -----------------
    #pragma unroll 1
    for (int r = 0; r < 25; r++) {
        int c = w + 16 * r;
        int q2 = lane + 32;
        float v1 = S[c * 50 + lane];
        float v2 = (q2 < LQ) ? S[c * 50 + q2] : 0.f;
        float m = (lane < qlen) ? v1 : -1e30f;
        if (q2 < LQ && q2 < qlen) m = fmaxf(m, v2);
        #pragma unroll
        for (int o = 16; o; o >>= 1) m = fmaxf(m, __shfl_xor_sync(~0u, m, o));
        float e1 = (lane < qlen) ? __expf(v1 - m) : 0.f;
        float e2 = (q2 < LQ && q2 < qlen) ? __expf(v2 - m) : 0.f;
        float s = e1 + e2;
        #pragma unroll
        for (int o = 16; o; o >>= 1) s += __shfl_xor_sync(~0u, s, o);
        float r1 = 1.f / s;
        e1 *= r1; e2 *= r1;
        S[c * 50 + lane] = e1;
        float* row = outSB + (size_t)(b * LC + c) * LQ;
        row[lane] = e1;
        if (q2 < LQ) { S[c * 50 + q2] = e2; row[q2] = e2; }
    }
    __syncthreads();

    // ---------------- Phase 5: c2q = Sbar@xq, q2c = Sbar@A, concat -----------
    #pragma unroll 1
    for (int pass = 0; pass < 7; pass++) {
        const int kmax = (pass < 6) ? 4 : 1;
        ull a1[4][2], a2[4][2];
        #pragma unroll
        for (int k = 0; k < 4; k++) {
            a1[k][0] = a1[k][1] = 0ull;
            a2[k][0] = a2[k][1] = 0ull;
        }
        const int cbase = pass * 64 + w;

        auto do_pair = [&](int q, const ull* XQ0u, const ull* XQ1u) {
            union { float4 f; ull u[2]; } AV0, AV1;
            AV0.f = *(const float4*)&A[q * 132 + lane * 4];
            AV1.f = *(const float4*)&A[(q + 1) * 132 + lane * 4];
            #pragma unroll
            for (int k = 0; k < 4; k++) {
                if (k < kmax) {
                    float2 sv = *(const float2*)&S[(cbase + 16 * k) * 50 + q];
                    ull s0 = pack2(sv.x, sv.x);
                    ull s1 = pack2(sv.y, sv.y);
                    fma2(a1[k][0], XQ0u[0], s0);
                    fma2(a1[k][1], XQ0u[1], s0);
                    fma2(a2[k][0], AV0.u[0], s0);
                    fma2(a2[k][1], AV0.u[1], s0);
                    fma2(a1[k][0], XQ1u[0], s1);
                    fma2(a1[k][1], XQ1u[1], s1);
                    fma2(a2[k][0], AV1.u[0], s1);
                    fma2(a2[k][1], AV1.u[1], s1);
                }
            }
        };

        #pragma unroll 1
        for (int q0 = 0; q0 < 48; q0 += 4) {
            union { float4 f; ull u[2]; } XQ0, XQ1, XQ2, XQ3;
            XQ0.f = __ldg((const float4*)(xqb + (size_t)q0 * DD) + lane);
            XQ1.f = __ldg((const float4*)(xqb + (size_t)(q0 + 1) * DD) + lane);
            XQ2.f = __ldg((const float4*)(xqb + (size_t)(q0 + 2) * DD) + lane);
            XQ3.f = __ldg((const float4*)(xqb + (size_t)(q0 + 3) * DD) + lane);
            do_pair(q0,     XQ0.u, XQ1.u);
            do_pair(q0 + 2, XQ2.u, XQ3.u);
        }
        {   // tail q = 48, 49
            union { float4 f; ull u[2]; } XQ0, XQ1;
            XQ0.f = __ldg((const float4*)(xqb + (size_t)48 * DD) + lane);
            XQ1.f = __ldg((const float4*)(xqb + (size_t)49 * DD) + lane);
            do_pair(48, XQ0.u, XQ1.u);
        }
        #pragma unroll
        for (int k = 0; k < 4; k++) {
            if (k < kmax) {
                int c = cbase + 16 * k;
                float4 xcv = __ldg((const float4*)(xcb + (size_t)c * DD) + lane);
                union { float4 f; ull u[2]; } C2Q, Q2C;
                C2Q.u[0] = a1[k][0]; C2Q.u[1] = a1[k][1];
                Q2C.u[0] = a2[k][0]; Q2C.u[1] = a2[k][1];
                float* base = out + ((size_t)b * LC + c) * (4 * DD) + lane * 4;
                *(float4*)(base)       = xcv;
                *(float4*)(base + 128) = C2Q.f;
                *(float4*)(base + 256) = make_float4(xcv.x * C2Q.f.x, xcv.y * C2Q.f.y,
                                                     xcv.z * C2Q.f.z, xcv.w * C2Q.f.w);
                *(float4*)(base + 384) = make_float4(xcv.x * Q2C.f.x, xcv.y * Q2C.f.y,
                                                     xcv.z * Q2C.f.z, xcv.w * Q2C.f.w);
            }
        }
    }
}

extern "C" void kernel_launch(void* const* d_in, const int* in_sizes, int n_in,
                              void* d_out, int out_size)
{
    const float* xc  = (const float*)d_in[0];
    const float* xq  = (const float*)d_in[1];
    const float* W0  = (const float*)d_in[2];
    const float* W1  = (const float*)d_in[3];
    const float* W2  = (const float*)d_in[4];
    const int* clen  = (const int*)d_in[5];
    const int* qlen  = (const int*)d_in[6];
    float* out = (float*)d_out;

    const size_t smem = (size_t)SM_TOT * sizeof(float);  // 108624 B
    cudaFuncSetAttribute(cqa6_kernel, cudaFuncAttributeMaxDynamicSharedMemorySize,
                         (int)smem);
    cqa6_kernel<<<NB, 512, smem>>>(xc, xq, W0, W1, W2, clen, qlen, out);
}

// round 14
// speedup vs baseline: 1.2585x; 1.0860x over previous
#include <cuda_runtime.h>
#include <cstdint>

typedef unsigned long long ull;

__device__ __forceinline__ ull pack2(float lo, float hi) {
    ull r; asm("mov.b64 %0, {%1, %2};" : "=l"(r) : "f"(lo), "f"(hi)); return r;
}
__device__ __forceinline__ void unpack2(ull v, float& lo, float& hi) {
    asm("mov.b64 {%0, %1}, %2;" : "=f"(lo), "=f"(hi) : "l"(v));
}
__device__ __forceinline__ void fma2(ull& d, ull a, ull b) {
    asm("fma.rn.f32x2 %0, %1, %2, %0;" : "+l"(d) : "l"(a), "l"(b));
}
__device__ __forceinline__ uint32_t s2u(const void* p) {
    return (uint32_t)__cvta_generic_to_shared(p);
}
__device__ __forceinline__ void cpa4(uint32_t dst, const float* src) {
    asm volatile("cp.async.ca.shared.global [%0], [%1], 4;" :: "r"(dst), "l"(src));
}
#define CP_COMMIT() asm volatile("cp.async.commit_group;" ::: "memory")
#define CP_WAIT0()  asm volatile("cp.async.wait_group 0;" ::: "memory")

#define NB 256
#define LC 400
#define LQ 50
#define DD 128
#define SM_TOT 27156   // floats: S 20000 | A/stb/xqW2T 6600 | sc 400 | sq 52 | mxc 52 | invc 52

__global__ __launch_bounds__(512, 2)
void cqa7_kernel(const float* __restrict__ g_xc, const float* __restrict__ g_xq,
                 const float* __restrict__ g_W0, const float* __restrict__ g_W1,
                 const float* __restrict__ g_W2, const int* __restrict__ g_clen,
                 const int* __restrict__ g_qlen, float* __restrict__ out)
{
    extern __shared__ float sm[];
    float* S    = sm;            // 400*50 packed
    float* A    = sm + 20000;    // 6600: ph0-1 xqW2T (128x51) / ph3 stb (50x129) / ph5 A (50x132)
    float* sc   = sm + 26600;
    float* sq   = sm + 27000;
    float* mxc  = sm + 27052;
    float* invc = sm + 27104;
    float* xqW2T = A;            // [d][q], stride 51, 128*51 = 6528
    // phase-1 xc staging lives inside S (dead until phase-1 writeback)
    float* stA0 = S;             // 8*404 = 3232 (16B-aligned rows)
    float* stA1 = S + 3232;

    const int b = blockIdx.x;
    const int t = threadIdx.x, lane = t & 31, w = t >> 5;
    const float* xcb = g_xc + (size_t)b * LC * DD;
    const float* xqb = g_xq + (size_t)b * LQ * DD;
    const int clen = g_clen[b];
    const int qlen = g_qlen[b];

    float* outSB = out + (size_t)NB * LC * 4 * DD;
    float* outST = outSB + (size_t)NB * LC * LQ;

    // ---- Phase 0: sc[c] = xc.W0, sq[q] = xq.W1, xqW2T[d][q] = xq[q][d]*W2[d]
    {
        float4 w0 = __ldg((const float4*)g_W0 + lane);
        #pragma unroll 2
        for (int r = 0; r < 25; r++) {
            int c = w + 16 * r;
            float4 v = __ldg((const float4*)(xcb + (size_t)c * DD) + lane);
            float p = v.x * w0.x + v.y * w0.y + v.z * w0.z + v.w * w0.w;
            #pragma unroll
            for (int o = 16; o; o >>= 1) p += __shfl_xor_sync(~0u, p, o);
            if (!lane) sc[c] = p;
        }
        float4 w1 = __ldg((const float4*)g_W1 + lane);
        #pragma unroll
        for (int r = 0; r < 4; r++) {
            int q = w + 16 * r;
            if (q < LQ) {
                float4 v = __ldg((const float4*)(xqb + (size_t)q * DD) + lane);
                float p = v.x * w1.x + v.y * w1.y + v.z * w1.z + v.w * w1.w;
                #pragma unroll
                for (int o = 16; o; o >>= 1) p += __shfl_xor_sync(~0u, p, o);
                if (!lane) sq[q] = p;
            }
        }
        #pragma unroll 1
        for (int i = t; i < LQ * 32; i += 512) {
            int q = i >> 5, d4 = i & 31;
            float4 v  = __ldg((const float4*)(xqb + (size_t)q * DD) + d4);
            float4 w2 = __ldg((const float4*)g_W2 + d4);
            xqW2T[(d4 * 4 + 0) * 51 + q] = v.x * w2.x;
            xqW2T[(d4 * 4 + 1) * 51 + q] = v.y * w2.y;
            xqW2T[(d4 * 4 + 2) * 51 + q] = v.z * w2.z;
            xqW2T[(d4 * 4 + 3) * 51 + q] = v.w * w2.w;
        }
    }

    // ---------------- Phase 1: S = xc @ (W2*xq)^T, cp.async double-buffered --
    ull acc[4][5];
    #pragma unroll
    for (int i = 0; i < 4; i++)
        #pragma unroll
        for (int j = 0; j < 5; j++) acc[i][j] = 0ull;
    const int ct = t / 10, qt = t - ct * 10;
    const bool act = t < 500;
    const int cb = ct * 8, qb = qt * 5;

    auto issue = [&](int s) {
        const int d0 = s * 8;
        float* bA = (s & 1) ? stA1 : stA0;
        #pragma unroll 1
        for (int i = t; i < LC * 8; i += 512) {
            int c = i >> 3, dd = i & 7;
            cpa4(s2u(bA + dd * 404 + c), xcb + (size_t)c * DD + d0 + dd);
        }
        CP_COMMIT();
    };

    __syncthreads();   // phase-0 writes (incl. xqW2T) visible
    issue(0);
    #pragma unroll 1
    for (int s = 0; s < 16; s++) {
        CP_WAIT0();
        __syncthreads();            // slice s staged & visible; prev compute done
        if (s < 15) issue(s + 1);   // overlaps with compute below
        const float* bA = (s & 1) ? stA1 : stA0;
        const float* bQ = xqW2T + (s * 8) * 51;
        if (act) {
            #pragma unroll
            for (int dd = 0; dd < 8; dd++) {
                union { float4 f; ull u[2]; } X0, X1;
                X0.f = *(const float4*)&bA[dd * 404 + cb];
                X1.f = *(const float4*)&bA[dd * 404 + cb + 4];
                #pragma unroll
                for (int j = 0; j < 5; j++) {
                    float xv = bQ[dd * 51 + qb + j];
                    ull bb = pack2(xv, xv);
                    fma2(acc[0][j], X0.u[0], bb);
                    fma2(acc[1][j], X0.u[1], bb);
                    fma2(acc[2][j], X1.u[0], bb);
                    fma2(acc[3][j], X1.u[1], bb);
                }
            }
        }
    }
    __syncthreads();
    if (act) {
        #pragma unroll
        for (int i = 0; i < 4; i++) {
            int c = cb + 2 * i;
            float s0 = sc[c], s1 = sc[c + 1];
            #pragma unroll
            for (int j = 0; j < 5; j++) {
                float lo, hi; unpack2(acc[i][j], lo, hi);
                int q = qb + j;
                S[c * 50 + q]       = lo + s0 + sq[q];
                S[(c + 1) * 50 + q] = hi + s1 + sq[q];
            }
        }
    }
    __syncthreads();

    // ---------------- Phase 2: column (over c) softmax stats -----------------
    #pragma unroll 1
    for (int r = 0; r < 4; r++) {
        int q = w + 16 * r;
        if (q < LQ) {
            float m = -1e30f, s = 0.f;
            for (int c = lane; c < clen; c += 32) {
                float v = S[c * 50 + q];
                if (v > m) { s = s * __expf(m - v) + 1.f; m = v; }
                else       { s += __expf(v - m); }
            }
            #pragma unroll
            for (int o = 16; o; o >>= 1) {
                float m2 = __shfl_xor_sync(~0u, m, o);
                float s2 = __shfl_xor_sync(~0u, s, o);
                if (m2 > m) { s = s * __expf(m - m2) + s2; m = m2; }
                else        { s += s2 * __expf(m2 - m); }
            }
            if (!lane) { mxc[q] = m; invc[q] = 1.f / s; }
        }
    }
    __syncthreads();

    // ------ Phase 3: S_T out + A = S_T @ x_cont (warp-groups split cc) -------
    {
        float* stb = A;   // 50*129 = 6450 <= 6600  (xqW2T dead now)
        const int g  = w >> 3;             // cc-half group
        const int wq = w & 7;
        const int nq = (wq < 2) ? 7 : 6;   // q = wq + 8j covers 0..49
        ull accA[7][2];
        #pragma unroll
        for (int j = 0; j < 7; j++) { accA[j][0] = 0ull; accA[j][1] = 0ull; }
        float* ST_b = outST + (size_t)b * LQ * LC;

        #pragma unroll 1
        for (int c0 = 0; c0 < LC; c0 += 128) {
            const int CHN = (LC - c0 >= 128) ? 128 : 16;
            __syncthreads();
            if (CHN == 128) {
                for (int i = t; i < LQ * 128; i += 512) {
                    int q = i >> 7, cc = i & 127, c = c0 + cc;
                    float v = (c < clen) ? __expf(S[c * 50 + q] - mxc[q]) * invc[q] : 0.f;
                    stb[q * 129 + cc] = v;
                    ST_b[(size_t)q * LC + c] = v;
                }
            } else {
                for (int i = t; i < LQ * 16; i += 512) {
                    int q = i >> 4, cc = i & 15, c = c0 + cc;
                    float v = (c < clen) ? __expf(S[c * 50 + q] - mxc[q]) * invc[q] : 0.f;
                    stb[q * 129 + cc] = v;
                    ST_b[(size_t)q * LC + c] = v;
                }
            }
            __syncthreads();
            const int ccb = g * (CHN >> 1);
            const int cce = ccb + (CHN >> 1);
            #pragma unroll 1
            for (int cc = ccb; cc < cce; cc += 4) {
                union { float4 f; ull u[2]; } X0, X1, X2, X3;
                X0.f = __ldg((const float4*)(xcb + (size_t)(c0 + cc) * DD) + lane);
                X1.f = __ldg((const float4*)(xcb + (size_t)(c0 + cc + 1) * DD) + lane);
                X2.f = __ldg((const float4*)(xcb + (size_t)(c0 + cc + 2) * DD) + lane);
                X3.f = __ldg((const float4*)(xcb + (size_t)(c0 + cc + 3) * DD) + lane);
                #pragma unroll
                for (int j = 0; j < 7; j++) {
                    if (j < nq) {
                        const float* sp = &stb[(wq + 8 * j) * 129 + cc];
                        ull p0 = pack2(sp[0], sp[0]);
                        ull p1 = pack2(sp[1], sp[1]);
                        ull p2 = pack2(sp[2], sp[2]);
                        ull p3 = pack2(sp[3], sp[3]);
                        fma2(accA[j][0], X0.u[0], p0);
                        fma2(accA[j][1], X0.u[1], p0);
                        fma2(accA[j][0], X1.u[0], p1);
                        fma2(accA[j][1], X1.u[1], p1);
                        fma2(accA[j][0], X2.u[0], p2);
                        fma2(accA[j][1], X2.u[1], p2);
                        fma2(accA[j][0], X3.u[0], p3);
                        fma2(accA[j][1], X3.u[1], p3);
                    }
                }
            }
        }
        __syncthreads();   // stb dead; A region reusable
        if (g == 0) {
            #pragma unroll
            for (int j = 0; j < 7; j++) {
                if (j < nq) {
                    union { float4 f; ull u[2]; } R;
                    R.u[0] = accA[j][0]; R.u[1] = accA[j][1];
                    *(float4*)&A[(wq + 8 * j) * 132 + lane * 4] = R.f;
                }
            }
        }
        __syncthreads();
        if (g == 1) {
            #pragma unroll
            for (int j = 0; j < 7; j++) {
                if (j < nq) {
                    union { float4 f; ull u[2]; } R;
                    R.u[0] = accA[j][0]; R.u[1] = accA[j][1];
                    float4 cur = *(const float4*)&A[(wq + 8 * j) * 132 + lane * 4];
                    R.f.x += cur.x; R.f.y += cur.y; R.f.z += cur.z; R.f.w += cur.w;
                    *(float4*)&A[(wq + 8 * j) * 132 + lane * 4] = R.f;
                }
            }
        }
    }
    __syncthreads();

    // ---------------- Phase 4: row softmax -> S_bar in place -----------------
    #pragma unroll 1
    for (int r = 0; r < 25; r++) {
        int c = w + 16 * r;
        int q2 = lane + 32;
        float v1 = S[c * 50 + lane];
        float v2 = (q2 < LQ) ? S[c * 50 + q2] : 0.f;
        float m = (lane < qlen) ? v1 : -1e30f;
        if (q2 < LQ && q2 < qlen) m = fmaxf(m, v2);
        #pragma unroll
        for (int o = 16; o; o >>= 1) m = fmaxf(m, __shfl_xor_sync(~0u, m, o));
        float e1 = (lane < qlen) ? __expf(v1 - m) : 0.f;
        float e2 = (q2 < LQ && q2 < qlen) ? __expf(v2 - m) : 0.f;
        float s = e1 + e2;
        #pragma unroll
        for (int o = 16; o; o >>= 1) s += __shfl_xor_sync(~0u, s, o);
        float r1 = 1.f / s;
        e1 *= r1; e2 *= r1;
        S[c * 50 + lane] = e1;
        float* row = outSB + (size_t)(b * LC + c) * LQ;
        row[lane] = e1;
        if (q2 < LQ) { S[c * 50 + q2] = e2; row[q2] = e2; }
    }
    __syncthreads();

    // ---- Phase 5: c2q/q2c + concat; warps split D in halves, kmax=10 --------
    {
        const int h  = w & 1;              // d-half
        const int cs = w >> 1;             // c-slot 0..7
        const int dbase = h * 64 + lane * 2;
        #pragma unroll 1
        for (int pass = 0; pass < 5; pass++) {
            ull a1[10], a2[10];
            #pragma unroll
            for (int k = 0; k < 10; k++) { a1[k] = 0ull; a2[k] = 0ull; }
            const int cb5 = pass * 80 + cs;    // c = cb5 + 8k, k<10
            #pragma unroll 1
            for (int q = 0; q < LQ; q += 2) {
                ull XQ0 = __ldg((const ull*)(xqb + (size_t)q * DD + dbase));
                ull XQ1 = __ldg((const ull*)(xqb + (size_t)(q + 1) * DD + dbase));
                ull AV0 = *(const ull*)&A[q * 132 + dbase];
                ull AV1 = *(const ull*)&A[(q + 1) * 132 + dbase];
                #pragma unroll
                for (int k = 0; k < 10; k++) {
                    float2 sv = *(const float2*)&S[(cb5 + 8 * k) * 50 + q];
                    ull s0 = pack2(sv.x, sv.x);
                    ull s1 = pack2(sv.y, sv.y);
                    fma2(a1[k], XQ0, s0);
                    fma2(a2[k], AV0, s0);
                    fma2(a1[k], XQ1, s1);
                    fma2(a2[k], AV1, s1);
                }
            }
            #pragma unroll
            for (int k = 0; k < 10; k++) {
                int c = cb5 + 8 * k;
                float2 xcv = __ldg((const float2*)(xcb + (size_t)c * DD + dbase));
                float cx, cy, qx, qy;
                unpack2(a1[k], cx, cy);
                unpack2(a2[k], qx, qy);
                float* base = out + ((size_t)b * LC + c) * (4 * DD) + dbase;
                *(float2*)(base)       = xcv;
                *(float2*)(base + 128) = make_float2(cx, cy);
                *(float2*)(base + 256) = make_float2(xcv.x * cx, xcv.y * cy);
                *(float2*)(base + 384) = make_float2(xcv.x * qx, xcv.y * qy);
            }
        }
    }
}

extern "C" void kernel_launch(void* const* d_in, const int* in_sizes, int n_in,
                              void* d_out, int out_size)
{
    const float* xc  = (const float*)d_in[0];
    const float* xq  = (const float*)d_in[1];
    const float* W0  = (const float*)d_in[2];
    const float* W1  = (const float*)d_in[3];
    const float* W2  = (const float*)d_in[4];
    const int* clen  = (const int*)d_in[5];
    const int* qlen  = (const int*)d_in[6];
    float* out = (float*)d_out;

    const size_t smem = (size_t)SM_TOT * sizeof(float);  // 108624 B
    cudaFuncSetAttribute(cqa7_kernel, cudaFuncAttributeMaxDynamicSharedMemorySize,
                         (int)smem);
    cqa7_kernel<<<NB, 512, smem>>>(xc, xq, W0, W1, W2, clen, qlen, out);
}

// round 16
// speedup vs baseline: 1.4165x; 1.1255x over previous
#include <cuda_runtime.h>
#include <cstdint>

typedef unsigned long long ull;

__device__ __forceinline__ ull pack2(float lo, float hi) {
    ull r; asm("mov.b64 %0, {%1, %2};" : "=l"(r) : "f"(lo), "f"(hi)); return r;
}
__device__ __forceinline__ void unpack2(ull v, float& lo, float& hi) {
    asm("mov.b64 {%0, %1}, %2;" : "=f"(lo), "=f"(hi) : "l"(v));
}
__device__ __forceinline__ void fma2(ull& d, ull a, ull b) {
    asm("fma.rn.f32x2 %0, %1, %2, %0;" : "+l"(d) : "l"(a), "l"(b));
}
__device__ __forceinline__ uint32_t s2u(const void* p) {
    return (uint32_t)__cvta_generic_to_shared(p);
}
__device__ __forceinline__ void cpa4(uint32_t dst, const float* src) {
    asm volatile("cp.async.ca.shared.global [%0], [%1], 4;" :: "r"(dst), "l"(src));
}
#define CP_COMMIT() asm volatile("cp.async.commit_group;" ::: "memory")
#define CP_WAIT0()  asm volatile("cp.async.wait_group 0;" ::: "memory")

#define NB 256
#define LC 400
#define LQ 50
#define DD 128
#define SM_TOT 27156   // floats: S 20000 | A/stb/xqW2T 6600 | sc 400 | sq 52 | mxc 52 | invc 52

__global__ __launch_bounds__(512, 2)
void cqa8_kernel(const float* __restrict__ g_xc, const float* __restrict__ g_xq,
                 const float* __restrict__ g_W0, const float* __restrict__ g_W1,
                 const float* __restrict__ g_W2, const int* __restrict__ g_clen,
                 const int* __restrict__ g_qlen, float* __restrict__ out)
{
    extern __shared__ float sm[];
    float* S    = sm;            // 400*50 packed
    float* A    = sm + 20000;    // 6600: ph0-1 xqW2T (128x51) / ph3 stb (50x129) / ph5 A (50x132)
    float* sc   = sm + 26600;
    float* sq   = sm + 27000;
    float* mxc  = sm + 27052;
    float* invc = sm + 27104;
    float* xqW2T = A;            // [d][q], stride 51, 128*51 = 6528
    // phase-1 xc staging lives inside S (dead until phase-1 writeback)
    float* stA0 = S;             // 8*404 = 3232 (16B-aligned rows)
    float* stA1 = S + 3232;

    const int b = blockIdx.x;
    const int t = threadIdx.x, lane = t & 31, w = t >> 5;
    const float* xcb = g_xc + (size_t)b * LC * DD;
    const float* xqb = g_xq + (size_t)b * LQ * DD;
    const int clen = g_clen[b];
    const int qlen = g_qlen[b];

    float* outSB = out + (size_t)NB * LC * 4 * DD;
    float* outST = outSB + (size_t)NB * LC * LQ;

    // ---- Phase 0: sc[c] = xc.W0, sq[q] = xq.W1, xqW2T[d][q] = xq[q][d]*W2[d]
    {
        float4 w0 = __ldg((const float4*)g_W0 + lane);
        #pragma unroll 2
        for (int r = 0; r < 25; r++) {
            int c = w + 16 * r;
            float4 v = __ldg((const float4*)(xcb + (size_t)c * DD) + lane);
            float p = v.x * w0.x + v.y * w0.y + v.z * w0.z + v.w * w0.w;
            #pragma unroll
            for (int o = 16; o; o >>= 1) p += __shfl_xor_sync(~0u, p, o);
            if (!lane) sc[c] = p;
        }
        float4 w1 = __ldg((const float4*)g_W1 + lane);
        #pragma unroll
        for (int r = 0; r < 4; r++) {
            int q = w + 16 * r;
            if (q < LQ) {
                float4 v = __ldg((const float4*)(xqb + (size_t)q * DD) + lane);
                float p = v.x * w1.x + v.y * w1.y + v.z * w1.z + v.w * w1.w;
                #pragma unroll
                for (int o = 16; o; o >>= 1) p += __shfl_xor_sync(~0u, p, o);
                if (!lane) sq[q] = p;
            }
        }
        #pragma unroll 1
        for (int i = t; i < LQ * 32; i += 512) {
            int q = i >> 5, d4 = i & 31;
            float4 v  = __ldg((const float4*)(xqb + (size_t)q * DD) + d4);
            float4 w2 = __ldg((const float4*)g_W2 + d4);
            xqW2T[(d4 * 4 + 0) * 51 + q] = v.x * w2.x;
            xqW2T[(d4 * 4 + 1) * 51 + q] = v.y * w2.y;
            xqW2T[(d4 * 4 + 2) * 51 + q] = v.z * w2.z;
            xqW2T[(d4 * 4 + 3) * 51 + q] = v.w * w2.w;
        }
    }

    // ---------------- Phase 1: S = xc @ (W2*xq)^T, cp.async double-buffered --
    ull acc[4][5];
    #pragma unroll
    for (int i = 0; i < 4; i++)
        #pragma unroll
        for (int j = 0; j < 5; j++) acc[i][j] = 0ull;
    const int ct = t / 10, qt = t - ct * 10;
    const bool act = t < 500;
    const int cb = ct * 8, qb = qt * 5;

    auto issue = [&](int s) {
        const int d0 = s * 8;
        float* bA = (s & 1) ? stA1 : stA0;
        #pragma unroll 1
        for (int i = t; i < LC * 8; i += 512) {
            int c = i >> 3, dd = i & 7;
            cpa4(s2u(bA + dd * 404 + c), xcb + (size_t)c * DD + d0 + dd);
        }
        CP_COMMIT();
    };

    __syncthreads();   // phase-0 writes (incl. xqW2T) visible
    issue(0);
    #pragma unroll 1
    for (int s = 0; s < 16; s++) {
        CP_WAIT0();
        __syncthreads();            // slice s staged & visible; prev compute done
        if (s < 15) issue(s + 1);   // overlaps with compute below
        const float* bA = (s & 1) ? stA1 : stA0;
        const float* bQ = xqW2T + (s * 8) * 51;
        if (act) {
            #pragma unroll
            for (int dd = 0; dd < 8; dd++) {
                union { float4 f; ull u[2]; } X0, X1;
                X0.f = *(const float4*)&bA[dd * 404 + cb];
                X1.f = *(const float4*)&bA[dd * 404 + cb + 4];
                #pragma unroll
                for (int j = 0; j < 5; j++) {
                    float xv = bQ[dd * 51 + qb + j];
                    ull bb = pack2(xv, xv);
                    fma2(acc[0][j], X0.u[0], bb);
                    fma2(acc[1][j], X0.u[1], bb);
                    fma2(acc[2][j], X1.u[0], bb);
                    fma2(acc[3][j], X1.u[1], bb);
                }
            }
        }
    }
    __syncthreads();
    if (act) {
        #pragma unroll
        for (int i = 0; i < 4; i++) {
            int c = cb + 2 * i;
            float s0 = sc[c], s1 = sc[c + 1];
            #pragma unroll
            for (int j = 0; j < 5; j++) {
                float lo, hi; unpack2(acc[i][j], lo, hi);
                int q = qb + j;
                S[c * 50 + q]       = lo + s0 + sq[q];
                S[(c + 1) * 50 + q] = hi + s1 + sq[q];
            }
        }
    }
    __syncthreads();

    // ---------------- Phase 2: column (over c) softmax stats -----------------
    #pragma unroll 1
    for (int r = 0; r < 4; r++) {
        int q = w + 16 * r;
        if (q < LQ) {
            float m = -1e30f, s = 0.f;
            for (int c = lane; c < clen; c += 32) {
                float v = S[c * 50 + q];
                if (v > m) { s = s * __expf(m - v) + 1.f; m = v; }
                else       { s += __expf(v - m); }
            }
            #pragma unroll
            for (int o = 16; o; o >>= 1) {
                float m2 = __shfl_xor_sync(~0u, m, o);
                float s2 = __shfl_xor_sync(~0u, s, o);
                if (m2 > m) { s = s * __expf(m - m2) + s2; m = m2; }
                else        { s += s2 * __expf(m2 - m); }
            }
            if (!lane) { mxc[q] = m; invc[q] = 1.f / s; }
        }
    }
    __syncthreads();

    // ------ Phase 3: S_T out + A = S_T @ x_cont (cc split, clen-bounded) -----
    {
        float* stb = A;   // 50*129 = 6450 <= 6600  (xqW2T dead now)
        const int g  = w >> 3;             // cc-half group
        const int wq = w & 7;
        const int nq = (wq < 2) ? 7 : 6;   // q = wq + 8j covers 0..49
        ull accA[7][2];
        #pragma unroll
        for (int j = 0; j < 7; j++) { accA[j][0] = 0ull; accA[j][1] = 0ull; }
        float* ST_b = outST + (size_t)b * LQ * LC;

        #pragma unroll 1
        for (int c0 = 0; c0 < LC; c0 += 128) {
            const int CHN = (LC - c0 >= 128) ? 128 : 16;
            __syncthreads();
            if (CHN == 128) {
                for (int i = t; i < LQ * 128; i += 512) {
                    int q = i >> 7, cc = i & 127, c = c0 + cc;
                    float v = (c < clen) ? __expf(S[c * 50 + q] - mxc[q]) * invc[q] : 0.f;
                    stb[q * 129 + cc] = v;
                    ST_b[(size_t)q * LC + c] = v;
                }
            } else {
                for (int i = t; i < LQ * 16; i += 512) {
                    int q = i >> 4, cc = i & 15, c = c0 + cc;
                    float v = (c < clen) ? __expf(S[c * 50 + q] - mxc[q]) * invc[q] : 0.f;
                    stb[q * 129 + cc] = v;
                    ST_b[(size_t)q * LC + c] = v;
                }
            }
            __syncthreads();
            // FMA loop bounded by clen: stb is exactly 0 for c >= clen
            const int ccb = g * (CHN >> 1);
            int cce = ccb + (CHN >> 1);
            {
                int cmax = ((clen - c0) + 3) & ~3;   // round up to unroll granule
                if (cmax < cce) cce = cmax;
            }
            #pragma unroll 1
            for (int cc = ccb; cc < cce; cc += 4) {
                union { float4 f; ull u[2]; } X0, X1, X2, X3;
                X0.f = __ldg((const float4*)(xcb + (size_t)(c0 + cc) * DD) + lane);
                X1.f = __ldg((const float4*)(xcb + (size_t)(c0 + cc + 1) * DD) + lane);
                X2.f = __ldg((const float4*)(xcb + (size_t)(c0 + cc + 2) * DD) + lane);
                X3.f = __ldg((const float4*)(xcb + (size_t)(c0 + cc + 3) * DD) + lane);
                #pragma unroll
                for (int j = 0; j < 7; j++) {
                    if (j < nq) {
                        const float* sp = &stb[(wq + 8 * j) * 129 + cc];
                        ull p0 = pack2(sp[0], sp[0]);
                        ull p1 = pack2(sp[1], sp[1]);
                        ull p2 = pack2(sp[2], sp[2]);
                        ull p3 = pack2(sp[3], sp[3]);
                        fma2(accA[j][0], X0.u[0], p0);
                        fma2(accA[j][1], X0.u[1], p0);
                        fma2(accA[j][0], X1.u[0], p1);
                        fma2(accA[j][1], X1.u[1], p1);
                        fma2(accA[j][0], X2.u[0], p2);
                        fma2(accA[j][1], X2.u[1], p2);
                        fma2(accA[j][0], X3.u[0], p3);
                        fma2(accA[j][1], X3.u[1], p3);
                    }
                }
            }
        }
        __syncthreads();   // stb dead; A region reusable
        if (g == 0) {
            #pragma unroll
            for (int j = 0; j < 7; j++) {
                if (j < nq) {
                    union { float4 f; ull u[2]; } R;
                    R.u[0] = accA[j][0]; R.u[1] = accA[j][1];
                    *(float4*)&A[(wq + 8 * j) * 132 + lane * 4] = R.f;
                }
            }
        }
        __syncthreads();
        if (g == 1) {
            #pragma unroll
            for (int j = 0; j < 7; j++) {
                if (j < nq) {
                    union { float4 f; ull u[2]; } R;
                    R.u[0] = accA[j][0]; R.u[1] = accA[j][1];
                    float4 cur = *(const float4*)&A[(wq + 8 * j) * 132 + lane * 4];
                    R.f.x += cur.x; R.f.y += cur.y; R.f.z += cur.z; R.f.w += cur.w;
                    *(float4*)&A[(wq + 8 * j) * 132 + lane * 4] = R.f;
                }
            }
        }
    }
    __syncthreads();

    // ---------------- Phase 4: row softmax -> S_bar in place -----------------
    #pragma unroll 1
    for (int r = 0; r < 25; r++) {
        int c = w + 16 * r;
        int q2 = lane + 32;
        float v1 = S[c * 50 + lane];
        float v2 = (q2 < LQ) ? S[c * 50 + q2] : 0.f;
        float m = (lane < qlen) ? v1 : -1e30f;
        if (q2 < LQ && q2 < qlen) m = fmaxf(m, v2);
        #pragma unroll
        for (int o = 16; o; o >>= 1) m = fmaxf(m, __shfl_xor_sync(~0u, m, o));
        float e1 = (lane < qlen) ? __expf(v1 - m) : 0.f;
        float e2 = (q2 < LQ && q2 < qlen) ? __expf(v2 - m) : 0.f;
        float s = e1 + e2;
        #pragma unroll
        for (int o = 16; o; o >>= 1) s += __shfl_xor_sync(~0u, s, o);
        float r1 = 1.f / s;
        e1 *= r1; e2 *= r1;
        S[c * 50 + lane] = e1;
        float* row = outSB + (size_t)(b * LC + c) * LQ;
        row[lane] = e1;
        if (q2 < LQ) { S[c * 50 + q2] = e2; row[q2] = e2; }
    }
    __syncthreads();

    // ---- Phase 5: c2q/q2c + concat; D-halved warps, kmax=10, qlen-bounded ---
    {
        const int h  = w & 1;              // d-half
        const int cs = w >> 1;             // c-slot 0..7
        const int dbase = h * 64 + lane * 2;
        const int qU = (qlen + 1) & ~1;    // S_bar[c][q] == 0 for q >= qlen
        #pragma unroll 1
        for (int pass = 0; pass < 5; pass++) {
            ull a1[10], a2[10];
            #pragma unroll
            for (int k = 0; k < 10; k++) { a1[k] = 0ull; a2[k] = 0ull; }
            const int cb5 = pass * 80 + cs;    // c = cb5 + 8k, k<10
            #pragma unroll 1
            for (int q = 0; q < qU; q += 2) {
                ull XQ0 = __ldg((const ull*)(xqb + (size_t)q * DD + dbase));
                ull XQ1 = __ldg((const ull*)(xqb + (size_t)(q + 1) * DD + dbase));
                ull AV0 = *(const ull*)&A[q * 132 + dbase];
                ull AV1 = *(const ull*)&A[(q + 1) * 132 + dbase];
                #pragma unroll
                for (int k = 0; k < 10; k++) {
                    float2 sv = *(const float2*)&S[(cb5 + 8 * k) * 50 + q];
                    ull s0 = pack2(sv.x, sv.x);
                    ull s1 = pack2(sv.y, sv.y);
                    fma2(a1[k], XQ0, s0);
                    fma2(a2[k], AV0, s0);
                    fma2(a1[k], XQ1, s1);
                    fma2(a2[k], AV1, s1);
                }
            }
            #pragma unroll
            for (int k = 0; k < 10; k++) {
                int c = cb5 + 8 * k;
                float2 xcv = __ldg((const float2*)(xcb + (size_t)c * DD + dbase));
                float cx, cy, qx, qy;
                unpack2(a1[k], cx, cy);
                unpack2(a2[k], qx, qy);
                float* base = out + ((size_t)b * LC + c) * (4 * DD) + dbase;
                *(float2*)(base)       = xcv;
                *(float2*)(base + 128) = make_float2(cx, cy);
                *(float2*)(base + 256) = make_float2(xcv.x * cx, xcv.y * cy);
                *(float2*)(base + 384) = make_float2(xcv.x * qx, xcv.y * qy);
            }
        }
    }
}

extern "C" void kernel_launch(void* const* d_in, const int* in_sizes, int n_in,
                              void* d_out, int out_size)
{
    const float* xc  = (const float*)d_in[0];
    const float* xq  = (const float*)d_in[1];
    const float* W0  = (const float*)d_in[2];
    const float* W1  = (const float*)d_in[3];
    const float* W2  = (const float*)d_in[4];
    const int* clen  = (const int*)d_in[5];
    const int* qlen  = (const int*)d_in[6];
    float* out = (float*)d_out;

    const size_t smem = (size_t)SM_TOT * sizeof(float);  // 108624 B
    cudaFuncSetAttribute(cqa8_kernel, cudaFuncAttributeMaxDynamicSharedMemorySize,
                         (int)smem);
    cqa8_kernel<<<NB, 512, smem>>>(xc, xq, W0, W1, W2, clen, qlen, out);
}